// round 5
// baseline (speedup 1.0000x reference)
#include <cuda_runtime.h>
#include <cuda_bf16.h>
#include <math.h>
#include <cstdint>

// ---------------- problem constants ----------------
constexpr int Bsz  = 2;
constexpr int Nq   = 2048;
constexpr int My   = 512;
constexpr int Cdim = 1536;
constexpr int Hn   = 12;
constexpr int HDim = 128;          // Cdim / Hn
constexpr int RD   = 64;
constexpr int Sk   = Nq + My;      // 2560
constexpr float EPSV  = 1e-6f;
constexpr float SCALE = 0.08838834764831845f;   // 1/sqrt(128)

// ---------------- scratch (static device arrays; no allocs allowed) ----------------
__device__ float g_qkv [(long long)Bsz * Nq * 3 * Cdim];
__device__ float g_kvr [(long long)Bsz * My * 2 * Cdim];
__device__ float g_Vb  [(long long)Bsz * Hn * Sk * HDim];   // V fp32 [bh][s][d]
__device__ float g_Sc  [(long long)Bsz * Hn * Nq * Sk];     // scores fp32
__device__ float g_yb  [Bsz * My];

// split-bf16 operand buffers
__device__ __nv_bfloat16 g_xh [(long long)Bsz * Nq * Cdim];
__device__ __nv_bfloat16 g_xl [(long long)Bsz * Nq * Cdim];
__device__ __nv_bfloat16 g_yh [(long long)Bsz * My * Cdim];
__device__ __nv_bfloat16 g_yl [(long long)Bsz * My * Cdim];
__device__ __nv_bfloat16 g_Wqkvh[(long long)3 * Cdim * Cdim];
__device__ __nv_bfloat16 g_Wqkvl[(long long)3 * Cdim * Cdim];
__device__ __nv_bfloat16 g_Wkvh [(long long)2 * Cdim * Cdim];
__device__ __nv_bfloat16 g_Wkvl [(long long)2 * Cdim * Cdim];
__device__ __nv_bfloat16 g_Wph  [(long long)Cdim * Cdim];
__device__ __nv_bfloat16 g_Wpl  [(long long)Cdim * Cdim];
__device__ __nv_bfloat16 g_Obh  [(long long)Bsz * Nq * Cdim];
__device__ __nv_bfloat16 g_Obl  [(long long)Bsz * Nq * Cdim];
// attention split operands
__device__ __nv_bfloat16 g_Qh [(long long)Bsz * Hn * Nq * HDim];
__device__ __nv_bfloat16 g_Ql [(long long)Bsz * Hn * Nq * HDim];
__device__ __nv_bfloat16 g_Kh [(long long)Bsz * Hn * Sk * HDim];
__device__ __nv_bfloat16 g_Kl [(long long)Bsz * Hn * Sk * HDim];
__device__ __nv_bfloat16 g_Vth[(long long)Bsz * Hn * HDim * Sk];  // V^T [bh][d][s]
__device__ __nv_bfloat16 g_Vtl[(long long)Bsz * Hn * HDim * Sk];
__device__ __nv_bfloat16 g_Ph [(long long)Bsz * Hn * Nq * Sk];
__device__ __nv_bfloat16 g_Pl [(long long)Bsz * Hn * Nq * Sk];

// ---------------- small PTX helpers (baseline PTX only) ----------------
__device__ __forceinline__ uint32_t smem_u32(const void* p) {
    uint32_t a;
    asm("{ .reg .u64 t; cvta.to.shared.u64 t, %1; cvt.u32.u64 %0, t; }" : "=r"(a) : "l"(p));
    return a;
}
__device__ __forceinline__ void cp16(uint32_t dst, const void* src) {
    asm volatile("cp.async.cg.shared.global [%0], [%1], 16;" :: "r"(dst), "l"(src));
}
#define CP_COMMIT()  asm volatile("cp.async.commit_group;" ::: "memory")
#define CP_WAIT(n)   asm volatile("cp.async.wait_group %0;" :: "n"(n) : "memory")

__device__ __forceinline__ void mma_bf16(float d[4], const uint32_t a[4], const uint32_t b[2]) {
    asm volatile(
        "mma.sync.aligned.m16n8k16.row.col.f32.bf16.bf16.f32 "
        "{%0,%1,%2,%3}, {%4,%5,%6,%7}, {%8,%9}, {%0,%1,%2,%3};"
        : "+f"(d[0]), "+f"(d[1]), "+f"(d[2]), "+f"(d[3])
        : "r"(a[0]), "r"(a[1]), "r"(a[2]), "r"(a[3]), "r"(b[0]), "r"(b[1]));
}
__device__ __forceinline__ void ldsm_x4(uint32_t& r0, uint32_t& r1, uint32_t& r2, uint32_t& r3,
                                        uint32_t addr) {
    asm volatile("ldmatrix.sync.aligned.m8n8.x4.shared.b16 {%0,%1,%2,%3}, [%4];"
        : "=r"(r0), "=r"(r1), "=r"(r2), "=r"(r3) : "r"(addr));
}

// ---------------- split-bf16 HMMA GEMM (batched, ldmatrix fragments) ----------------
// C[M,N] = A[M,K] @ W[K,N]; A=(Ah,Al) row-major [M,K] (lda==Kd);
// W=(Bh,Bl) row-major TRANSPOSED [N,K] (ldb==Kd). fp32 accumulate, 3-product split.
// EPI: 0 = fp32 out, 1 = fp32 out + bias, 2 = split-bf16 out (Coh/Col).
constexpr int MM_STRIDE_B = 80;                         // 40 bf16 per smem row
constexpr int MM_ARR_B    = 128 * MM_STRIDE_B;          // 10240 per operand array
constexpr int MM_BUF_B    = 4 * MM_ARR_B;               // Ah,Al,Bh,Bl
constexpr int MM_SMEM_B   = 2 * MM_BUF_B;               // 81920

template<int EPI>
__global__ __launch_bounds__(256)
void mma_gemm(const __nv_bfloat16* __restrict__ Ah, const __nv_bfloat16* __restrict__ Al,
              const __nv_bfloat16* __restrict__ Bh, const __nv_bfloat16* __restrict__ Bl,
              float* __restrict__ C, const float* __restrict__ bias,
              __nv_bfloat16* __restrict__ Coh, __nv_bfloat16* __restrict__ Col,
              int Kd, int ldc,
              long long sA, long long sB, long long sCout, long long sCin, int cPeriod)
{
    extern __shared__ char smem[];
    const uint32_t sbase = smem_u32(smem);

    const int z = blockIdx.z;
    Ah += (long long)z * sA;  Al += (long long)z * sA;
    Bh += (long long)z * sB;  Bl += (long long)z * sB;
    const long long coff = (long long)(z / cPeriod) * sCout + (long long)(z % cPeriod) * sCin;
    if (EPI == 2) { Coh += coff; Col += coff; } else { C += coff; }

    const int tid  = threadIdx.x;
    const int lane = tid & 31;
    const int wid  = tid >> 5;
    const int row0 = blockIdx.y * 128;
    const int col0 = blockIdx.x * 128;
    const int wm   = (wid >> 2) * 64;     // 0 / 64
    const int wn   = (wid & 3) * 32;      // 0..96
    const int g    = lane >> 2;           // 0..7
    const int tg   = lane & 3;            // 0..3

    // staging map: each thread moves 2 16B segments per operand array per chunk
    const int s0   = tid * 2;
    const int row_s0 = s0 >> 2,  q_s0 = s0 & 3;
    const int row_s1 = (s0 + 1) >> 2, q_s1 = (s0 + 1) & 3;

    auto stage = [&](int c, int buf) {
        const long long k0 = (long long)c * 32;
        const uint32_t db = sbase + buf * MM_BUF_B;
        {
            const long long ga = (long long)(row0 + row_s0) * Kd + k0 + q_s0 * 8;
            const long long gb = (long long)(col0 + row_s0) * Kd + k0 + q_s0 * 8;
            const uint32_t  so = row_s0 * MM_STRIDE_B + q_s0 * 16;
            cp16(db + 0 * MM_ARR_B + so, Ah + ga);
            cp16(db + 1 * MM_ARR_B + so, Al + ga);
            cp16(db + 2 * MM_ARR_B + so, Bh + gb);
            cp16(db + 3 * MM_ARR_B + so, Bl + gb);
        }
        {
            const long long ga = (long long)(row0 + row_s1) * Kd + k0 + q_s1 * 8;
            const long long gb = (long long)(col0 + row_s1) * Kd + k0 + q_s1 * 8;
            const uint32_t  so = row_s1 * MM_STRIDE_B + q_s1 * 16;
            cp16(db + 0 * MM_ARR_B + so, Ah + ga);
            cp16(db + 1 * MM_ARR_B + so, Al + ga);
            cp16(db + 2 * MM_ARR_B + so, Bh + gb);
            cp16(db + 3 * MM_ARR_B + so, Bl + gb);
        }
    };

    float acc[4][4][4];
    #pragma unroll
    for (int i = 0; i < 4; i++)
        #pragma unroll
        for (int j = 0; j < 4; j++)
            #pragma unroll
            for (int r = 0; r < 4; r++) acc[i][j][r] = 0.f;

    // ldmatrix per-lane address components
    const int rA = lane & 15;             // A: row within 16-row tile
    const int cA = (lane >> 4) * 16;      // A: k half (bytes)
    const int grp = lane >> 3;            // B groups
    const int rB = (grp >> 1) * 8 + (lane & 7);   // B: row within 16-row pair
    const int cB = (grp & 1) * 16;        // B: k half (bytes)

    const int nch = Kd / 32;
    stage(0, 0);
    CP_COMMIT();

    for (int c = 0; c < nch; c++) {
        if (c + 1 < nch) { stage(c + 1, (c + 1) & 1); CP_COMMIT(); CP_WAIT(1); }
        else             { CP_WAIT(0); }
        __syncthreads();

        const uint32_t bp = sbase + (c & 1) * MM_BUF_B;

        #pragma unroll
        for (int kk = 0; kk < 2; kk++) {
            uint32_t ah[4][4], al[4][4], bh[4][2], bl[4][2];
            #pragma unroll
            for (int mt = 0; mt < 4; mt++) {
                uint32_t addr = bp + (wm + mt * 16 + rA) * MM_STRIDE_B + kk * 32 + cA;
                ldsm_x4(ah[mt][0], ah[mt][1], ah[mt][2], ah[mt][3], addr);
                ldsm_x4(al[mt][0], al[mt][1], al[mt][2], al[mt][3], addr + MM_ARR_B);
            }
            #pragma unroll
            for (int p = 0; p < 2; p++) {
                uint32_t addr = bp + 2 * MM_ARR_B
                              + (wn + p * 16 + rB) * MM_STRIDE_B + kk * 32 + cB;
                ldsm_x4(bh[2*p][0], bh[2*p][1], bh[2*p+1][0], bh[2*p+1][1], addr);
                ldsm_x4(bl[2*p][0], bl[2*p][1], bl[2*p+1][0], bl[2*p+1][1], addr + MM_ARR_B);
            }
            #pragma unroll
            for (int mt = 0; mt < 4; mt++)
                #pragma unroll
                for (int nt = 0; nt < 4; nt++) {
                    mma_bf16(acc[mt][nt], ah[mt], bh[nt]);
                    mma_bf16(acc[mt][nt], ah[mt], bl[nt]);
                    mma_bf16(acc[mt][nt], al[mt], bh[nt]);
                }
        }
        __syncthreads();
    }

    // ---- epilogue ----
    #pragma unroll
    for (int nt = 0; nt < 4; nt++) {
        const int col = col0 + wn + nt * 8 + 2 * tg;
        float b0 = 0.f, b1 = 0.f;
        if (EPI == 1) { b0 = bias[col]; b1 = bias[col + 1]; }
        #pragma unroll
        for (int mt = 0; mt < 4; mt++) {
            const int r = row0 + wm + mt * 16 + g;
            if (EPI == 2) {
                #pragma unroll
                for (int hh = 0; hh < 2; hh++) {
                    const float va = acc[mt][nt][hh * 2 + 0];
                    const float vb = acc[mt][nt][hh * 2 + 1];
                    const long long o = (long long)(r + hh * 8) * ldc + col;
                    const __nv_bfloat16 ha = __float2bfloat16(va);
                    const __nv_bfloat16 hb = __float2bfloat16(vb);
                    __nv_bfloat162 hv; hv.x = ha; hv.y = hb;
                    __nv_bfloat162 lv;
                    lv.x = __float2bfloat16(va - __bfloat162float(ha));
                    lv.y = __float2bfloat16(vb - __bfloat162float(hb));
                    *(__nv_bfloat162*)(Coh + o) = hv;
                    *(__nv_bfloat162*)(Col + o) = lv;
                }
            } else {
                float2 v0, v1;
                v0.x = acc[mt][nt][0] + b0; v0.y = acc[mt][nt][1] + b1;
                v1.x = acc[mt][nt][2] + b0; v1.y = acc[mt][nt][3] + b1;
                *(float2*)(C + (long long)r * ldc + col)       = v0;
                *(float2*)(C + (long long)(r + 8) * ldc + col) = v1;
            }
        }
    }
}

// ---------------- fp32 -> split bf16 (row-major keep) ----------------
__global__ void cvt_split(const float* __restrict__ src, __nv_bfloat16* __restrict__ h,
                          __nv_bfloat16* __restrict__ l, long long n)
{
    const long long i = ((long long)blockIdx.x * blockDim.x + threadIdx.x) * 4;
    if (i >= n) return;
    const float4 v = *(const float4*)(src + i);
    __nv_bfloat16 hb[4], lb[4];
    const float f[4] = {v.x, v.y, v.z, v.w};
    #pragma unroll
    for (int j = 0; j < 4; j++) {
        hb[j] = __float2bfloat16(f[j]);
        lb[j] = __float2bfloat16(f[j] - __bfloat162float(hb[j]));
    }
    *(uint2*)(h + i) = *(uint2*)hb;
    *(uint2*)(l + i) = *(uint2*)lb;
}

// ---------------- fp32 [K][N] -> split bf16 transposed [N][K] ----------------
__global__ void cvt_split_T(const float* __restrict__ W, __nv_bfloat16* __restrict__ h,
                            __nv_bfloat16* __restrict__ l, int K, int N)
{
    __shared__ float tile[32][33];
    const int k0 = blockIdx.y * 32;
    const int n0 = blockIdx.x * 32;
    const int tx = threadIdx.x;
    const int ty = threadIdx.y;
    #pragma unroll
    for (int i = ty; i < 32; i += 8)
        tile[i][tx] = W[(long long)(k0 + i) * N + n0 + tx];
    __syncthreads();
    #pragma unroll
    for (int i = ty; i < 32; i += 8) {
        const float v = tile[tx][i];
        const __nv_bfloat16 hb = __float2bfloat16(v);
        const __nv_bfloat16 lb = __float2bfloat16(v - __bfloat162float(hb));
        const long long o = (long long)(n0 + i) * K + k0 + tx;
        h[o] = hb; l[o] = lb;
    }
}

// ---------------- V: fp32 [bh][s][d] -> split bf16 transposed [bh][d][s] ----------
__global__ void v_transpose_split(const float* __restrict__ Vb,
                                  __nv_bfloat16* __restrict__ Vth,
                                  __nv_bfloat16* __restrict__ Vtl)
{
    __shared__ float tile[32][33];
    const int z  = blockIdx.z;
    const int ss0 = blockIdx.x * 32;
    const int dd0 = blockIdx.y * 32;
    const int tx = threadIdx.x;
    const int ty = threadIdx.y;
    const long long ib = (long long)z * Sk * HDim;
    const long long ob = (long long)z * HDim * Sk;
    #pragma unroll
    for (int i = ty; i < 32; i += 8)
        tile[i][tx] = Vb[ib + (long long)(ss0 + i) * HDim + dd0 + tx];
    __syncthreads();
    #pragma unroll
    for (int i = ty; i < 32; i += 8) {
        const float v = tile[tx][i];
        const __nv_bfloat16 hb = __float2bfloat16(v);
        const __nv_bfloat16 lb = __float2bfloat16(v - __bfloat162float(hb));
        const long long o = ob + (long long)(dd0 + i) * Sk + ss0 + tx;
        Vth[o] = hb; Vtl[o] = lb;
    }
}

// ---------------- warp reduction helpers ----------------
__device__ __forceinline__ float warpSum(float v) {
    #pragma unroll
    for (int o = 16; o > 0; o >>= 1) v += __shfl_xor_sync(0xffffffffu, v, o);
    return v;
}
__device__ __forceinline__ float warpMax(float v) {
    #pragma unroll
    for (int o = 16; o > 0; o >>= 1) v = fmaxf(v, __shfl_xor_sync(0xffffffffu, v, o));
    return v;
}
__device__ __forceinline__ void split_write(float v, __nv_bfloat16* h, __nv_bfloat16* l, long long idx) {
    const __nv_bfloat16 hb = __float2bfloat16(v);
    h[idx] = hb;
    l[idx] = __float2bfloat16(v - __bfloat162float(hb));
}

// ---------------- QKV postprocess: RMSNorm + RoPE -> split bf16 Q,K; fp32 V ------
__global__ void qkv_post(const float* __restrict__ qkv, const float* __restrict__ pos,
                         const float* __restrict__ qw, const float* __restrict__ kw,
                         __nv_bfloat16* __restrict__ Qh, __nv_bfloat16* __restrict__ Ql,
                         __nv_bfloat16* __restrict__ Kh, __nv_bfloat16* __restrict__ Kl,
                         float* __restrict__ Vb)
{
    const int idx = blockIdx.x;
    const int h  = idx % Hn;
    const int bn = idx / Hn;
    const int n  = bn % Nq;
    const int b  = bn / Nq;
    const int d  = threadIdx.x;

    const float* row = qkv + (long long)bn * (3 * Cdim);
    const float qv = row[h * HDim + d];
    const float kv = row[Cdim + h * HDim + d];
    const float vv = row[2 * Cdim + h * HDim + d];

    __shared__ float sred[8];
    __shared__ float qs[HDim], ks[HDim];

    const float sq = warpSum(qv * qv);
    const float sk = warpSum(kv * kv);
    const int lane = d & 31, w = d >> 5;
    if (lane == 0) { sred[w] = sq; sred[4 + w] = sk; }
    __syncthreads();
    const float sumq = sred[0] + sred[1] + sred[2] + sred[3];
    const float sumk = sred[4] + sred[5] + sred[6] + sred[7];
    const float rq = rsqrtf(sumq * (1.0f / HDim) + EPSV);
    const float rk = rsqrtf(sumk * (1.0f / HDim) + EPSV);
    const float qn = qw[d] * qv * rq;
    const float kn = kw[d] * kv * rk;
    qs[d] = qn; ks[d] = kn;
    __syncthreads();

    float qo = qn, ko = kn;
    if (d < RD) {
        const int j = d & 31;
        const float c = pos[(n * 32 + j) * 2 + 0];
        const float s = pos[(n * 32 + j) * 2 + 1];
        if (d < RD / 2) { qo = qs[d] * c - qs[d + 32] * s;  ko = ks[d] * c - ks[d + 32] * s; }
        else            { qo = qs[d - 32] * s + qs[d] * c;  ko = ks[d - 32] * s + ks[d] * c; }
    }
    const long long qi = (((long long)(b * Hn + h)) * Nq + n) * HDim + d;
    const long long ki = (((long long)(b * Hn + h)) * Sk + n) * HDim + d;
    split_write(qo, Qh, Ql, qi);
    split_write(ko, Kh, Kl, ki);
    Vb[ki] = vv;
}

// ---------------- KV(y) postprocess ----------------
__global__ void kv_post(const float* __restrict__ kvr, const float* __restrict__ kw,
                        __nv_bfloat16* __restrict__ Kh, __nv_bfloat16* __restrict__ Kl,
                        float* __restrict__ Vb)
{
    const int idx = blockIdx.x;
    const int h  = idx % Hn;
    const int bm = idx / Hn;
    const int m  = bm % My;
    const int b  = bm / My;
    const int d  = threadIdx.x;

    const float* row = kvr + (long long)bm * (2 * Cdim);
    const float kv = row[h * HDim + d];
    const float vv = row[Cdim + h * HDim + d];

    __shared__ float sred[4];
    const float sk = warpSum(kv * kv);
    if ((d & 31) == 0) sred[d >> 5] = sk;
    __syncthreads();
    const float sumk = sred[0] + sred[1] + sred[2] + sred[3];
    const float rk = rsqrtf(sumk * (1.0f / HDim) + EPSV);
    const float kn = kw[d] * kv * rk;

    const long long ki = (((long long)(b * Hn + h)) * Sk + (Nq + m)) * HDim + d;
    split_write(kn, Kh, Kl, ki);
    Vb[ki] = vv;
}

__global__ void ybias_kernel(const float* __restrict__ ytw, float* __restrict__ yb)
{
    const int i = blockIdx.x * blockDim.x + threadIdx.x;
    if (i < Bsz * My) yb[i] = logf(fmaxf(ytw[i], 1e-4f));
}

// ---------------- softmax (scale + bias fused) -> split bf16 P ----------------
__global__ __launch_bounds__(256)
void softmax_kernel(const float* __restrict__ Sc, const float* __restrict__ yb,
                    __nv_bfloat16* __restrict__ Ph, __nv_bfloat16* __restrict__ Pl)
{
    const long long row = blockIdx.x;
    const int b = (int)(row / ((long long)Hn * Nq));
    const float* p = Sc + row * Sk;
    const int tid = threadIdx.x;

    float v[Sk / 256];
    float mx = -1e30f;
    #pragma unroll
    for (int i = 0; i < Sk / 256; i++) {
        const int col = tid + i * 256;
        float t = p[col] * SCALE;
        if (col >= Nq) t += yb[b * My + col - Nq];
        v[i] = t; mx = fmaxf(mx, t);
    }

    __shared__ float s[8];
    mx = warpMax(mx);
    if ((tid & 31) == 0) s[tid >> 5] = mx;
    __syncthreads();
    float mfull = s[0];
    #pragma unroll
    for (int w = 1; w < 8; w++) mfull = fmaxf(mfull, s[w]);
    __syncthreads();

    float sum = 0.f;
    #pragma unroll
    for (int i = 0; i < Sk / 256; i++) { v[i] = __expf(v[i] - mfull); sum += v[i]; }
    sum = warpSum(sum);
    if ((tid & 31) == 0) s[tid >> 5] = sum;
    __syncthreads();
    float tot = s[0];
    #pragma unroll
    for (int w = 1; w < 8; w++) tot += s[w];
    const float inv = 1.0f / tot;

    __nv_bfloat16* ph = Ph + row * Sk;
    __nv_bfloat16* pl = Pl + row * Sk;
    #pragma unroll
    for (int i = 0; i < Sk / 256; i++) {
        const int col = tid + i * 256;
        const float pv = v[i] * inv;
        const __nv_bfloat16 hb = __float2bfloat16(pv);
        ph[col] = hb;
        pl[col] = __float2bfloat16(pv - __bfloat162float(hb));
    }
}

// ---------------- launch ----------------
extern "C" void kernel_launch(void* const* d_in, const int* in_sizes, int n_in,
                              void* d_out, int out_size)
{
    const float* x    = (const float*)d_in[0];
    const float* y    = (const float*)d_in[1];
    const float* pos  = (const float*)d_in[2];
    const float* ytw  = (const float*)d_in[3];
    const float* Wqkv = (const float*)d_in[4];
    const float* Wkv  = (const float*)d_in[5];
    const float* qw   = (const float*)d_in[6];
    const float* kw   = (const float*)d_in[7];
    const float* Wproj= (const float*)d_in[8];
    const float* bproj= (const float*)d_in[9];
    float* out = (float*)d_out;

    float *qkv, *kvr, *Vb, *Sc, *yb;
    cudaGetSymbolAddress((void**)&qkv, g_qkv);
    cudaGetSymbolAddress((void**)&kvr, g_kvr);
    cudaGetSymbolAddress((void**)&Vb,  g_Vb);
    cudaGetSymbolAddress((void**)&Sc,  g_Sc);
    cudaGetSymbolAddress((void**)&yb,  g_yb);

    __nv_bfloat16 *xh,*xl,*yh,*yl,*Wqh,*Wql,*Wkh,*Wkl,*Wph,*Wpl,*Obh,*Obl;
    __nv_bfloat16 *Qh,*Ql,*Kh,*Kl,*Vth,*Vtl,*Ph,*Pl;
    cudaGetSymbolAddress((void**)&xh, g_xh);   cudaGetSymbolAddress((void**)&xl, g_xl);
    cudaGetSymbolAddress((void**)&yh, g_yh);   cudaGetSymbolAddress((void**)&yl, g_yl);
    cudaGetSymbolAddress((void**)&Wqh, g_Wqkvh); cudaGetSymbolAddress((void**)&Wql, g_Wqkvl);
    cudaGetSymbolAddress((void**)&Wkh, g_Wkvh);  cudaGetSymbolAddress((void**)&Wkl, g_Wkvl);
    cudaGetSymbolAddress((void**)&Wph, g_Wph);   cudaGetSymbolAddress((void**)&Wpl, g_Wpl);
    cudaGetSymbolAddress((void**)&Obh, g_Obh);   cudaGetSymbolAddress((void**)&Obl, g_Obl);
    cudaGetSymbolAddress((void**)&Qh, g_Qh);     cudaGetSymbolAddress((void**)&Ql, g_Ql);
    cudaGetSymbolAddress((void**)&Kh, g_Kh);     cudaGetSymbolAddress((void**)&Kl, g_Kl);
    cudaGetSymbolAddress((void**)&Vth, g_Vth);   cudaGetSymbolAddress((void**)&Vtl, g_Vtl);
    cudaGetSymbolAddress((void**)&Ph, g_Ph);     cudaGetSymbolAddress((void**)&Pl, g_Pl);

    cudaFuncSetAttribute(mma_gemm<0>, cudaFuncAttributeMaxDynamicSharedMemorySize, MM_SMEM_B);
    cudaFuncSetAttribute(mma_gemm<1>, cudaFuncAttributeMaxDynamicSharedMemorySize, MM_SMEM_B);
    cudaFuncSetAttribute(mma_gemm<2>, cudaFuncAttributeMaxDynamicSharedMemorySize, MM_SMEM_B);

    const long long sQ  = (long long)Nq * HDim;
    const long long sKV = (long long)Sk * HDim;
    const long long sSc = (long long)Nq * Sk;

    // 0) split conversions
    auto cvt = [&](const float* s, __nv_bfloat16* h, __nv_bfloat16* l, long long n) {
        cvt_split<<<(int)((n / 4 + 255) / 256), 256>>>(s, h, l, n);
    };
    cvt(x, xh, xl, (long long)Bsz * Nq * Cdim);
    cvt(y, yh, yl, (long long)Bsz * My * Cdim);
    cvt_split_T<<<dim3(3 * Cdim / 32, Cdim / 32), dim3(32, 8)>>>(Wqkv, Wqh, Wql, Cdim, 3 * Cdim);
    cvt_split_T<<<dim3(2 * Cdim / 32, Cdim / 32), dim3(32, 8)>>>(Wkv,  Wkh, Wkl, Cdim, 2 * Cdim);
    cvt_split_T<<<dim3(Cdim / 32,     Cdim / 32), dim3(32, 8)>>>(Wproj, Wph, Wpl, Cdim, Cdim);

    // 1) QKV = x @ Wqkv
    mma_gemm<0><<<dim3(3 * Cdim / 128, Bsz * Nq / 128, 1), 256, MM_SMEM_B>>>(
        xh, xl, Wqh, Wql, qkv, nullptr, nullptr, nullptr, Cdim, 3 * Cdim, 0, 0, 0, 0, 1);

    // 2) KV = y @ Wkv
    mma_gemm<0><<<dim3(2 * Cdim / 128, Bsz * My / 128, 1), 256, MM_SMEM_B>>>(
        yh, yl, Wkh, Wkl, kvr, nullptr, nullptr, nullptr, Cdim, 2 * Cdim, 0, 0, 0, 0, 1);

    // 3) postprocess
    qkv_post<<<Bsz * Nq * Hn, HDim>>>(qkv, pos, qw, kw, Qh, Ql, Kh, Kl, Vb);
    kv_post<<<Bsz * My * Hn, HDim>>>(kvr, kw, Kh, Kl, Vb);
    ybias_kernel<<<(Bsz * My + 255) / 256, 256>>>(ytw, yb);
    v_transpose_split<<<dim3(Sk / 32, HDim / 32, Bsz * Hn), dim3(32, 8)>>>(Vb, Vth, Vtl);

    // 4) scores = Q @ K^T  batched over 24 (b,h)
    mma_gemm<0><<<dim3(Sk / 128, Nq / 128, Bsz * Hn), 256, MM_SMEM_B>>>(
        Qh, Ql, Kh, Kl, Sc, nullptr, nullptr, nullptr, HDim, Sk, sQ, sKV, sSc, 0, 1);

    // 5) softmax -> split bf16 P
    softmax_kernel<<<Bsz * Hn * Nq, 256>>>(Sc, yb, Ph, Pl);

    // 6) O = P @ V  batched, writes split-bf16 O directly into [b][n][h*128]
    mma_gemm<2><<<dim3(HDim / 128, Nq / 128, Bsz * Hn), 256, MM_SMEM_B>>>(
        Ph, Pl, Vth, Vtl, nullptr, nullptr, Obh, Obl, Sk, Cdim,
        sSc, sKV, (long long)Nq * Cdim, (long long)HDim, Hn);

    // 7) out = O @ Wproj + bproj
    mma_gemm<1><<<dim3(Cdim / 128, Bsz * Nq / 128, 1), 256, MM_SMEM_B>>>(
        Obh, Obl, Wph, Wpl, out, bproj, nullptr, nullptr, Cdim, Cdim, 0, 0, 0, 0, 1);
}

// round 6
// speedup vs baseline: 1.2141x; 1.2141x over previous
#include <cuda_runtime.h>
#include <cuda_bf16.h>
#include <math.h>
#include <cstdint>

// ---------------- problem constants ----------------
constexpr int Bsz  = 2;
constexpr int Nq   = 2048;
constexpr int My   = 512;
constexpr int Cdim = 1536;
constexpr int Hn   = 12;
constexpr int HDim = 128;          // Cdim / Hn
constexpr int RD   = 64;
constexpr int Sk   = Nq + My;      // 2560
constexpr float EPSV  = 1e-6f;
constexpr float SCALE = 0.08838834764831845f;   // 1/sqrt(128)

// ---------------- scratch (static device arrays; no allocs allowed) ----------------
__device__ float g_qkv [(long long)Bsz * Nq * 3 * Cdim];
__device__ float g_kvr [(long long)Bsz * My * 2 * Cdim];
__device__ float g_Vb  [(long long)Bsz * Hn * Sk * HDim];   // V fp32 [bh][s][d]
__device__ float g_yb  [Bsz * My];

// split-bf16 operand buffers
__device__ __nv_bfloat16 g_xh [(long long)Bsz * Nq * Cdim];
__device__ __nv_bfloat16 g_xl [(long long)Bsz * Nq * Cdim];
__device__ __nv_bfloat16 g_yh [(long long)Bsz * My * Cdim];
__device__ __nv_bfloat16 g_yl [(long long)Bsz * My * Cdim];
__device__ __nv_bfloat16 g_Wqkvh[(long long)3 * Cdim * Cdim];
__device__ __nv_bfloat16 g_Wqkvl[(long long)3 * Cdim * Cdim];
__device__ __nv_bfloat16 g_Wkvh [(long long)2 * Cdim * Cdim];
__device__ __nv_bfloat16 g_Wkvl [(long long)2 * Cdim * Cdim];
__device__ __nv_bfloat16 g_Wph  [(long long)Cdim * Cdim];
__device__ __nv_bfloat16 g_Wpl  [(long long)Cdim * Cdim];
__device__ __nv_bfloat16 g_Obh  [(long long)Bsz * Nq * Cdim];
__device__ __nv_bfloat16 g_Obl  [(long long)Bsz * Nq * Cdim];
// attention split operands
__device__ __nv_bfloat16 g_Qh [(long long)Bsz * Hn * Nq * HDim];
__device__ __nv_bfloat16 g_Ql [(long long)Bsz * Hn * Nq * HDim];
__device__ __nv_bfloat16 g_Kh [(long long)Bsz * Hn * Sk * HDim];
__device__ __nv_bfloat16 g_Kl [(long long)Bsz * Hn * Sk * HDim];
__device__ __nv_bfloat16 g_Vth[(long long)Bsz * Hn * HDim * Sk];  // V^T [bh][d][s]
__device__ __nv_bfloat16 g_Vtl[(long long)Bsz * Hn * HDim * Sk];

// ---------------- small PTX helpers (baseline PTX only) ----------------
__device__ __forceinline__ uint32_t smem_u32(const void* p) {
    uint32_t a;
    asm("{ .reg .u64 t; cvta.to.shared.u64 t, %1; cvt.u32.u64 %0, t; }" : "=r"(a) : "l"(p));
    return a;
}
__device__ __forceinline__ void cp16(uint32_t dst, const void* src) {
    asm volatile("cp.async.cg.shared.global [%0], [%1], 16;" :: "r"(dst), "l"(src));
}
#define CP_COMMIT()  asm volatile("cp.async.commit_group;" ::: "memory")
#define CP_WAIT(n)   asm volatile("cp.async.wait_group %0;" :: "n"(n) : "memory")

__device__ __forceinline__ void mma_bf16(float d[4], const uint32_t a[4], const uint32_t b[2]) {
    asm volatile(
        "mma.sync.aligned.m16n8k16.row.col.f32.bf16.bf16.f32 "
        "{%0,%1,%2,%3}, {%4,%5,%6,%7}, {%8,%9}, {%0,%1,%2,%3};"
        : "+f"(d[0]), "+f"(d[1]), "+f"(d[2]), "+f"(d[3])
        : "r"(a[0]), "r"(a[1]), "r"(a[2]), "r"(a[3]), "r"(b[0]), "r"(b[1]));
}

// ---------------- split-bf16 HMMA GEMM (weight GEMMs; R4-proven LDS loads) --------
constexpr int MM_STRIDE_B = 80;
constexpr int MM_ARR_B    = 128 * MM_STRIDE_B;
constexpr int MM_BUF_B    = 4 * MM_ARR_B;
constexpr int MM_SMEM_B   = 2 * MM_BUF_B;   // 81920

template<bool ADD_BIAS>
__global__ __launch_bounds__(256)
void mma_gemm(const __nv_bfloat16* __restrict__ Ah, const __nv_bfloat16* __restrict__ Al,
              const __nv_bfloat16* __restrict__ Bh, const __nv_bfloat16* __restrict__ Bl,
              float* __restrict__ C, const float* __restrict__ bias,
              int Kd, int ldc)
{
    extern __shared__ char smem[];
    const uint32_t sbase = smem_u32(smem);

    const int tid  = threadIdx.x;
    const int lane = tid & 31;
    const int wid  = tid >> 5;
    const int row0 = blockIdx.y * 128;
    const int col0 = blockIdx.x * 128;
    const int wm   = (wid >> 2) * 64;
    const int wn   = (wid & 3) * 32;
    const int g    = lane >> 2;
    const int tg   = lane & 3;

    const int s0   = tid * 2;
    const int row_s0 = s0 >> 2,  q_s0 = s0 & 3;
    const int row_s1 = (s0 + 1) >> 2, q_s1 = (s0 + 1) & 3;

    auto stage = [&](int c, int buf) {
        const long long k0 = (long long)c * 32;
        const uint32_t db = sbase + buf * MM_BUF_B;
        {
            const long long ga = (long long)(row0 + row_s0) * Kd + k0 + q_s0 * 8;
            const long long gb = (long long)(col0 + row_s0) * Kd + k0 + q_s0 * 8;
            const uint32_t  so = row_s0 * MM_STRIDE_B + q_s0 * 16;
            cp16(db + 0 * MM_ARR_B + so, Ah + ga);
            cp16(db + 1 * MM_ARR_B + so, Al + ga);
            cp16(db + 2 * MM_ARR_B + so, Bh + gb);
            cp16(db + 3 * MM_ARR_B + so, Bl + gb);
        }
        {
            const long long ga = (long long)(row0 + row_s1) * Kd + k0 + q_s1 * 8;
            const long long gb = (long long)(col0 + row_s1) * Kd + k0 + q_s1 * 8;
            const uint32_t  so = row_s1 * MM_STRIDE_B + q_s1 * 16;
            cp16(db + 0 * MM_ARR_B + so, Ah + ga);
            cp16(db + 1 * MM_ARR_B + so, Al + ga);
            cp16(db + 2 * MM_ARR_B + so, Bh + gb);
            cp16(db + 3 * MM_ARR_B + so, Bl + gb);
        }
    };

    float acc[4][4][4];
    #pragma unroll
    for (int i = 0; i < 4; i++)
        #pragma unroll
        for (int j = 0; j < 4; j++)
            #pragma unroll
            for (int r = 0; r < 4; r++) acc[i][j][r] = 0.f;

    const int nch = Kd / 32;
    stage(0, 0);
    CP_COMMIT();

    for (int c = 0; c < nch; c++) {
        if (c + 1 < nch) { stage(c + 1, (c + 1) & 1); CP_COMMIT(); CP_WAIT(1); }
        else             { CP_WAIT(0); }
        __syncthreads();

        const char* bp = smem + (c & 1) * MM_BUF_B;
        const char* pAh = bp;
        const char* pAl = bp + MM_ARR_B;
        const char* pBh = bp + 2 * MM_ARR_B;
        const char* pBl = bp + 3 * MM_ARR_B;

        #pragma unroll
        for (int kk = 0; kk < 2; kk++) {
            const int cbyte = (kk * 16 + 2 * tg) * 2;
            uint32_t ah[4][4], al[4][4], bh[4][2], bl[4][2];
            #pragma unroll
            for (int mt = 0; mt < 4; mt++) {
                const int r = wm + mt * 16 + g;
                ah[mt][0] = *(const uint32_t*)(pAh + r * MM_STRIDE_B + cbyte);
                ah[mt][1] = *(const uint32_t*)(pAh + (r + 8) * MM_STRIDE_B + cbyte);
                ah[mt][2] = *(const uint32_t*)(pAh + r * MM_STRIDE_B + cbyte + 16);
                ah[mt][3] = *(const uint32_t*)(pAh + (r + 8) * MM_STRIDE_B + cbyte + 16);
                al[mt][0] = *(const uint32_t*)(pAl + r * MM_STRIDE_B + cbyte);
                al[mt][1] = *(const uint32_t*)(pAl + (r + 8) * MM_STRIDE_B + cbyte);
                al[mt][2] = *(const uint32_t*)(pAl + r * MM_STRIDE_B + cbyte + 16);
                al[mt][3] = *(const uint32_t*)(pAl + (r + 8) * MM_STRIDE_B + cbyte + 16);
            }
            #pragma unroll
            for (int nt = 0; nt < 4; nt++) {
                const int n = wn + nt * 8 + g;
                bh[nt][0] = *(const uint32_t*)(pBh + n * MM_STRIDE_B + cbyte);
                bh[nt][1] = *(const uint32_t*)(pBh + n * MM_STRIDE_B + cbyte + 16);
                bl[nt][0] = *(const uint32_t*)(pBl + n * MM_STRIDE_B + cbyte);
                bl[nt][1] = *(const uint32_t*)(pBl + n * MM_STRIDE_B + cbyte + 16);
            }
            #pragma unroll
            for (int mt = 0; mt < 4; mt++)
                #pragma unroll
                for (int nt = 0; nt < 4; nt++) {
                    mma_bf16(acc[mt][nt], ah[mt], bh[nt]);
                    mma_bf16(acc[mt][nt], ah[mt], bl[nt]);
                    mma_bf16(acc[mt][nt], al[mt], bh[nt]);
                }
        }
        __syncthreads();
    }

    #pragma unroll
    for (int nt = 0; nt < 4; nt++) {
        const int col = col0 + wn + nt * 8 + 2 * tg;
        float b0 = 0.f, b1 = 0.f;
        if (ADD_BIAS) { b0 = bias[col]; b1 = bias[col + 1]; }
        #pragma unroll
        for (int mt = 0; mt < 4; mt++) {
            const int r = row0 + wm + mt * 16 + g;
            float2 v0, v1;
            v0.x = acc[mt][nt][0] + b0; v0.y = acc[mt][nt][1] + b1;
            v1.x = acc[mt][nt][2] + b0; v1.y = acc[mt][nt][3] + b1;
            *(float2*)(C + (long long)r * ldc + col)       = v0;
            *(float2*)(C + (long long)(r + 8) * ldc + col) = v1;
        }
    }
}

// ---------------- fused attention: S = QK^T, exp(+bias), O = P V, normalize ------
// Grid: (Nq/128, Bsz*Hn). Block 256. exp WITHOUT max-subtraction (scores bounded
// by ~12.1 because Q,K are RMS-normalized), so no online rescaling is needed.
constexpr int FA_NIT = Sk / 64;                 // 40 key blocks of 64
constexpr int FQ   = 0;                          // Q hi: 128 x 272B
constexpr int FQL  = 34816;                      // Q lo
constexpr int FK   = 69632;                      // K bufs: 2 x (hi 64x272 + lo)
constexpr int FKHALF = 17408;
constexpr int FKBUF  = 34816;
constexpr int FV   = 139264;                     // V^T hi: 128 x 144B
constexpr int FVL  = 157696;                     // V^T lo
constexpr int FP   = 176128;                     // P hi: 128 x 144B
constexpr int FPL  = 194560;                     // P lo
constexpr int FRS  = 212992;                     // rowsums: 2 x 128 floats
constexpr int FYB  = 214016;                     // yb: 512 floats
constexpr int FA_SMEM = 216064;

__global__ __launch_bounds__(256, 1)
void fused_attn(const __nv_bfloat16* __restrict__ Qh, const __nv_bfloat16* __restrict__ Ql,
                const __nv_bfloat16* __restrict__ Kh, const __nv_bfloat16* __restrict__ Kl,
                const __nv_bfloat16* __restrict__ Vth, const __nv_bfloat16* __restrict__ Vtl,
                const float* __restrict__ yb,
                __nv_bfloat16* __restrict__ Obh, __nv_bfloat16* __restrict__ Obl)
{
    extern __shared__ char smem[];
    const uint32_t sb = smem_u32(smem);

    const int z  = blockIdx.y;
    const int q0 = blockIdx.x * 128;
    const int b  = z / Hn;
    const int h  = z % Hn;

    const int tid  = threadIdx.x;
    const int lane = tid & 31;
    const int wid  = tid >> 5;
    const int g    = lane >> 2;
    const int tg   = lane & 3;
    const int wm   = (wid >> 1) * 32;      // q-rows of this warp (S and O phases)
    const int wn   = (wid & 1) * 32;       // S-phase key cols
    const int wn2  = (wid & 1) * 64;       // O-phase d cols

    const __nv_bfloat16* Qhp = Qh + (long long)z * Nq * HDim;
    const __nv_bfloat16* Qlp = Ql + (long long)z * Nq * HDim;
    const __nv_bfloat16* Khp = Kh + (long long)z * Sk * HDim;
    const __nv_bfloat16* Klp = Kl + (long long)z * Sk * HDim;
    const __nv_bfloat16* Vhp = Vth + (long long)z * HDim * Sk;
    const __nv_bfloat16* Vlp = Vtl + (long long)z * HDim * Sk;

    // preload y bias block
    float* sYB = (float*)(smem + FYB);
    sYB[tid]       = yb[b * My + tid];
    sYB[tid + 256] = yb[b * My + tid + 256];

    // prologue: Q tile (whole kernel) + K(0)
    #pragma unroll
    for (int j = 0; j < 8; j++) {
        const int id = tid + j * 256, r = id >> 4, c = id & 15;
        cp16(sb + FQ  + r * 272 + c * 16, Qhp + (long long)(q0 + r) * HDim + c * 8);
        cp16(sb + FQL + r * 272 + c * 16, Qlp + (long long)(q0 + r) * HDim + c * 8);
    }
    #pragma unroll
    for (int j = 0; j < 4; j++) {
        const int id = tid + j * 256, r = id >> 4, c = id & 15;
        cp16(sb + FK +          r * 272 + c * 16, Khp + (long long)r * HDim + c * 8);
        cp16(sb + FK + FKHALF + r * 272 + c * 16, Klp + (long long)r * HDim + c * 8);
    }
    CP_COMMIT();

    float oacc[2][8][4];
    #pragma unroll
    for (int i = 0; i < 2; i++)
        #pragma unroll
        for (int j = 0; j < 8; j++)
            #pragma unroll
            for (int r = 0; r < 4; r++) oacc[i][j][r] = 0.f;
    float rowsum[4] = {0.f, 0.f, 0.f, 0.f};

    for (int it = 0; it < FA_NIT; it++) {
        __syncthreads();                       // V buffer + P free (prev PV done)
        // issue V(it) and K(it+1) as one group
        #pragma unroll
        for (int j = 0; j < 4; j++) {
            const int id = tid + j * 256, d = id >> 3, c = id & 7;
            cp16(sb + FV  + d * 144 + c * 16, Vhp + (long long)d * Sk + it * 64 + c * 8);
            cp16(sb + FVL + d * 144 + c * 16, Vlp + (long long)d * Sk + it * 64 + c * 8);
        }
        if (it + 1 < FA_NIT) {
            const int sblk = (it + 1) * 64;
            const uint32_t kb = sb + FK + ((it + 1) & 1) * FKBUF;
            #pragma unroll
            for (int j = 0; j < 4; j++) {
                const int id = tid + j * 256, r = id >> 4, c = id & 15;
                cp16(kb +          r * 272 + c * 16, Khp + (long long)(sblk + r) * HDim + c * 8);
                cp16(kb + FKHALF + r * 272 + c * 16, Klp + (long long)(sblk + r) * HDim + c * 8);
            }
        }
        CP_COMMIT();
        CP_WAIT(1);                            // K(it) (and Q on it=0) ready
        __syncthreads();

        // ---- S phase: S = Q K(it)^T (split-bf16, 3 products) ----
        const char* kbp = smem + FK + (it & 1) * FKBUF;
        float sacc[2][4][4];
        #pragma unroll
        for (int i = 0; i < 2; i++)
            #pragma unroll
            for (int j = 0; j < 4; j++)
                #pragma unroll
                for (int r = 0; r < 4; r++) sacc[i][j][r] = 0.f;

        #pragma unroll
        for (int kk = 0; kk < 8; kk++) {
            const int cb = kk * 32 + tg * 4;
            uint32_t qh_[2][4], ql_[2][4], kh_[4][2], kl_[4][2];
            #pragma unroll
            for (int mt = 0; mt < 2; mt++) {
                const char* p = smem + FQ + (wm + mt * 16 + g) * 272 + cb;
                qh_[mt][0] = *(const uint32_t*)(p);
                qh_[mt][1] = *(const uint32_t*)(p + 8 * 272);
                qh_[mt][2] = *(const uint32_t*)(p + 16);
                qh_[mt][3] = *(const uint32_t*)(p + 8 * 272 + 16);
                ql_[mt][0] = *(const uint32_t*)(p + FQL);
                ql_[mt][1] = *(const uint32_t*)(p + FQL + 8 * 272);
                ql_[mt][2] = *(const uint32_t*)(p + FQL + 16);
                ql_[mt][3] = *(const uint32_t*)(p + FQL + 8 * 272 + 16);
            }
            #pragma unroll
            for (int nt = 0; nt < 4; nt++) {
                const char* p = kbp + (wn + nt * 8 + g) * 272 + cb;
                kh_[nt][0] = *(const uint32_t*)(p);
                kh_[nt][1] = *(const uint32_t*)(p + 16);
                kl_[nt][0] = *(const uint32_t*)(p + FKHALF);
                kl_[nt][1] = *(const uint32_t*)(p + FKHALF + 16);
            }
            #pragma unroll
            for (int mt = 0; mt < 2; mt++)
                #pragma unroll
                for (int nt = 0; nt < 4; nt++) {
                    mma_bf16(sacc[mt][nt], qh_[mt], kh_[nt]);
                    mma_bf16(sacc[mt][nt], qh_[mt], kl_[nt]);
                    mma_bf16(sacc[mt][nt], ql_[mt], kh_[nt]);
                }
        }

        // ---- exp (+scale +bias), write split P to smem, accumulate row sums ----
        #pragma unroll
        for (int mt = 0; mt < 2; mt++) {
            #pragma unroll
            for (int nt = 0; nt < 4; nt++) {
                const int col0 = wn + nt * 8 + 2 * tg;
                const int gc   = it * 64 + col0;      // gc even; Nq even
                float b0 = 0.f, b1 = 0.f;
                if (gc >= Nq) { b0 = sYB[gc - Nq]; b1 = sYB[gc - Nq + 1]; }
                const float p0 = __expf(sacc[mt][nt][0] * SCALE + b0);
                const float p1 = __expf(sacc[mt][nt][1] * SCALE + b1);
                const float p2 = __expf(sacc[mt][nt][2] * SCALE + b0);
                const float p3 = __expf(sacc[mt][nt][3] * SCALE + b1);
                rowsum[mt * 2 + 0] += p0 + p1;
                rowsum[mt * 2 + 1] += p2 + p3;
                const int r0 = wm + mt * 16 + g;
                __nv_bfloat162 hv, lv;
                hv.x = __float2bfloat16(p0); hv.y = __float2bfloat16(p1);
                lv.x = __float2bfloat16(p0 - __bfloat162float(hv.x));
                lv.y = __float2bfloat16(p1 - __bfloat162float(hv.y));
                *(__nv_bfloat162*)(smem + FP  + r0 * 144 + col0 * 2) = hv;
                *(__nv_bfloat162*)(smem + FPL + r0 * 144 + col0 * 2) = lv;
                hv.x = __float2bfloat16(p2); hv.y = __float2bfloat16(p3);
                lv.x = __float2bfloat16(p2 - __bfloat162float(hv.x));
                lv.y = __float2bfloat16(p3 - __bfloat162float(hv.y));
                *(__nv_bfloat162*)(smem + FP  + (r0 + 8) * 144 + col0 * 2) = hv;
                *(__nv_bfloat162*)(smem + FPL + (r0 + 8) * 144 + col0 * 2) = lv;
            }
        }

        CP_WAIT(0);                            // V(it) (and K(it+1)) ready
        __syncthreads();                       // P visible to all warps

        // ---- PV phase: O += P V(it) (split-bf16, 3 products) ----
        #pragma unroll
        for (int kk = 0; kk < 4; kk++) {
            const int cb = kk * 32 + tg * 4;
            uint32_t ph_[2][4], pl_[2][4], vh_[8][2], vl_[8][2];
            #pragma unroll
            for (int mt = 0; mt < 2; mt++) {
                const char* p = smem + FP + (wm + mt * 16 + g) * 144 + cb;
                ph_[mt][0] = *(const uint32_t*)(p);
                ph_[mt][1] = *(const uint32_t*)(p + 8 * 144);
                ph_[mt][2] = *(const uint32_t*)(p + 16);
                ph_[mt][3] = *(const uint32_t*)(p + 8 * 144 + 16);
                const char* q = p + (FPL - FP);
                pl_[mt][0] = *(const uint32_t*)(q);
                pl_[mt][1] = *(const uint32_t*)(q + 8 * 144);
                pl_[mt][2] = *(const uint32_t*)(q + 16);
                pl_[mt][3] = *(const uint32_t*)(q + 8 * 144 + 16);
            }
            #pragma unroll
            for (int nt = 0; nt < 8; nt++) {
                const char* p = smem + FV + (wn2 + nt * 8 + g) * 144 + cb;
                vh_[nt][0] = *(const uint32_t*)(p);
                vh_[nt][1] = *(const uint32_t*)(p + 16);
                vl_[nt][0] = *(const uint32_t*)(p + (FVL - FV));
                vl_[nt][1] = *(const uint32_t*)(p + (FVL - FV) + 16);
            }
            #pragma unroll
            for (int mt = 0; mt < 2; mt++)
                #pragma unroll
                for (int nt = 0; nt < 8; nt++) {
                    mma_bf16(oacc[mt][nt], ph_[mt], vh_[nt]);
                    mma_bf16(oacc[mt][nt], ph_[mt], vl_[nt]);
                    mma_bf16(oacc[mt][nt], pl_[mt], vh_[nt]);
                }
        }
    }

    // ---- combine row sums across the two n-warps ----
    #pragma unroll
    for (int j = 0; j < 4; j++) {
        rowsum[j] += __shfl_xor_sync(0xffffffffu, rowsum[j], 1);
        rowsum[j] += __shfl_xor_sync(0xffffffffu, rowsum[j], 2);
    }
    float* sRS = (float*)(smem + FRS);
    if (tg == 0) {
        sRS[(wid & 1) * 128 + wm + g]      = rowsum[0];
        sRS[(wid & 1) * 128 + wm + g + 8]  = rowsum[1];
        sRS[(wid & 1) * 128 + wm + g + 16] = rowsum[2];
        sRS[(wid & 1) * 128 + wm + g + 24] = rowsum[3];
    }
    __syncthreads();

    // ---- epilogue: normalize, split-bf16 write into [b][n][h*128 + d] ----
    #pragma unroll
    for (int mt = 0; mt < 2; mt++) {
        const int r = wm + mt * 16 + g;
        const float inv0 = 1.f / (sRS[r]     + sRS[128 + r]);
        const float inv1 = 1.f / (sRS[r + 8] + sRS[128 + r + 8]);
        #pragma unroll
        for (int nt = 0; nt < 8; nt++) {
            const int col = wn2 + nt * 8 + 2 * tg;
            const long long o0 = ((long long)b * Nq + q0 + r) * Cdim + h * HDim + col;
            const long long o1 = o0 + 8LL * Cdim;
            const float a0 = oacc[mt][nt][0] * inv0, a1 = oacc[mt][nt][1] * inv0;
            const float a2 = oacc[mt][nt][2] * inv1, a3 = oacc[mt][nt][3] * inv1;
            __nv_bfloat162 hv, lv;
            hv.x = __float2bfloat16(a0); hv.y = __float2bfloat16(a1);
            lv.x = __float2bfloat16(a0 - __bfloat162float(hv.x));
            lv.y = __float2bfloat16(a1 - __bfloat162float(hv.y));
            *(__nv_bfloat162*)(Obh + o0) = hv;
            *(__nv_bfloat162*)(Obl + o0) = lv;
            hv.x = __float2bfloat16(a2); hv.y = __float2bfloat16(a3);
            lv.x = __float2bfloat16(a2 - __bfloat162float(hv.x));
            lv.y = __float2bfloat16(a3 - __bfloat162float(hv.y));
            *(__nv_bfloat162*)(Obh + o1) = hv;
            *(__nv_bfloat162*)(Obl + o1) = lv;
        }
    }
}

// ---------------- fp32 -> split bf16 (row-major keep) ----------------
__global__ void cvt_split(const float* __restrict__ src, __nv_bfloat16* __restrict__ h,
                          __nv_bfloat16* __restrict__ l, long long n)
{
    const long long i = ((long long)blockIdx.x * blockDim.x + threadIdx.x) * 4;
    if (i >= n) return;
    const float4 v = *(const float4*)(src + i);
    __nv_bfloat16 hb[4], lb[4];
    const float f[4] = {v.x, v.y, v.z, v.w};
    #pragma unroll
    for (int j = 0; j < 4; j++) {
        hb[j] = __float2bfloat16(f[j]);
        lb[j] = __float2bfloat16(f[j] - __bfloat162float(hb[j]));
    }
    *(uint2*)(h + i) = *(uint2*)hb;
    *(uint2*)(l + i) = *(uint2*)lb;
}

// ---------------- fp32 [K][N] -> split bf16 transposed [N][K] ----------------
__global__ void cvt_split_T(const float* __restrict__ W, __nv_bfloat16* __restrict__ h,
                            __nv_bfloat16* __restrict__ l, int K, int N)
{
    __shared__ float tile[32][33];
    const int k0 = blockIdx.y * 32;
    const int n0 = blockIdx.x * 32;
    const int tx = threadIdx.x;
    const int ty = threadIdx.y;
    #pragma unroll
    for (int i = ty; i < 32; i += 8)
        tile[i][tx] = W[(long long)(k0 + i) * N + n0 + tx];
    __syncthreads();
    #pragma unroll
    for (int i = ty; i < 32; i += 8) {
        const float v = tile[tx][i];
        const __nv_bfloat16 hb = __float2bfloat16(v);
        const __nv_bfloat16 lb = __float2bfloat16(v - __bfloat162float(hb));
        const long long o = (long long)(n0 + i) * K + k0 + tx;
        h[o] = hb; l[o] = lb;
    }
}

// ---------------- V: fp32 [bh][s][d] -> split bf16 transposed [bh][d][s] ----------
__global__ void v_transpose_split(const float* __restrict__ Vb,
                                  __nv_bfloat16* __restrict__ Vth,
                                  __nv_bfloat16* __restrict__ Vtl)
{
    __shared__ float tile[32][33];
    const int z  = blockIdx.z;
    const int ss0 = blockIdx.x * 32;
    const int dd0 = blockIdx.y * 32;
    const int tx = threadIdx.x;
    const int ty = threadIdx.y;
    const long long ib = (long long)z * Sk * HDim;
    const long long ob = (long long)z * HDim * Sk;
    #pragma unroll
    for (int i = ty; i < 32; i += 8)
        tile[i][tx] = Vb[ib + (long long)(ss0 + i) * HDim + dd0 + tx];
    __syncthreads();
    #pragma unroll
    for (int i = ty; i < 32; i += 8) {
        const float v = tile[tx][i];
        const __nv_bfloat16 hb = __float2bfloat16(v);
        const __nv_bfloat16 lb = __float2bfloat16(v - __bfloat162float(hb));
        const long long o = ob + (long long)(dd0 + i) * Sk + ss0 + tx;
        Vth[o] = hb; Vtl[o] = lb;
    }
}

// ---------------- warp reduction helpers ----------------
__device__ __forceinline__ float warpSum(float v) {
    #pragma unroll
    for (int o = 16; o > 0; o >>= 1) v += __shfl_xor_sync(0xffffffffu, v, o);
    return v;
}
__device__ __forceinline__ void split_write(float v, __nv_bfloat16* h, __nv_bfloat16* l, long long idx) {
    const __nv_bfloat16 hb = __float2bfloat16(v);
    h[idx] = hb;
    l[idx] = __float2bfloat16(v - __bfloat162float(hb));
}

// ---------------- QKV postprocess: RMSNorm + RoPE -> split bf16 Q,K; fp32 V ------
__global__ void qkv_post(const float* __restrict__ qkv, const float* __restrict__ pos,
                         const float* __restrict__ qw, const float* __restrict__ kw,
                         __nv_bfloat16* __restrict__ Qh, __nv_bfloat16* __restrict__ Ql,
                         __nv_bfloat16* __restrict__ Kh, __nv_bfloat16* __restrict__ Kl,
                         float* __restrict__ Vb)
{
    const int idx = blockIdx.x;
    const int h  = idx % Hn;
    const int bn = idx / Hn;
    const int n  = bn % Nq;
    const int b  = bn / Nq;
    const int d  = threadIdx.x;

    const float* row = qkv + (long long)bn * (3 * Cdim);
    const float qv = row[h * HDim + d];
    const float kv = row[Cdim + h * HDim + d];
    const float vv = row[2 * Cdim + h * HDim + d];

    __shared__ float sred[8];
    __shared__ float qs[HDim], ks[HDim];

    const float sq = warpSum(qv * qv);
    const float sk = warpSum(kv * kv);
    const int lane = d & 31, w = d >> 5;
    if (lane == 0) { sred[w] = sq; sred[4 + w] = sk; }
    __syncthreads();
    const float sumq = sred[0] + sred[1] + sred[2] + sred[3];
    const float sumk = sred[4] + sred[5] + sred[6] + sred[7];
    const float rq = rsqrtf(sumq * (1.0f / HDim) + EPSV);
    const float rk = rsqrtf(sumk * (1.0f / HDim) + EPSV);
    const float qn = qw[d] * qv * rq;
    const float kn = kw[d] * kv * rk;
    qs[d] = qn; ks[d] = kn;
    __syncthreads();

    float qo = qn, ko = kn;
    if (d < RD) {
        const int j = d & 31;
        const float c = pos[(n * 32 + j) * 2 + 0];
        const float s = pos[(n * 32 + j) * 2 + 1];
        if (d < RD / 2) { qo = qs[d] * c - qs[d + 32] * s;  ko = ks[d] * c - ks[d + 32] * s; }
        else            { qo = qs[d - 32] * s + qs[d] * c;  ko = ks[d - 32] * s + ks[d] * c; }
    }
    const long long qi = (((long long)(b * Hn + h)) * Nq + n) * HDim + d;
    const long long ki = (((long long)(b * Hn + h)) * Sk + n) * HDim + d;
    split_write(qo, Qh, Ql, qi);
    split_write(ko, Kh, Kl, ki);
    Vb[ki] = vv;
}

// ---------------- KV(y) postprocess ----------------
__global__ void kv_post(const float* __restrict__ kvr, const float* __restrict__ kw,
                        __nv_bfloat16* __restrict__ Kh, __nv_bfloat16* __restrict__ Kl,
                        float* __restrict__ Vb)
{
    const int idx = blockIdx.x;
    const int h  = idx % Hn;
    const int bm = idx / Hn;
    const int m  = bm % My;
    const int b  = bm / My;
    const int d  = threadIdx.x;

    const float* row = kvr + (long long)bm * (2 * Cdim);
    const float kv = row[h * HDim + d];
    const float vv = row[Cdim + h * HDim + d];

    __shared__ float sred[4];
    const float sk = warpSum(kv * kv);
    if ((d & 31) == 0) sred[d >> 5] = sk;
    __syncthreads();
    const float sumk = sred[0] + sred[1] + sred[2] + sred[3];
    const float rk = rsqrtf(sumk * (1.0f / HDim) + EPSV);
    const float kn = kw[d] * kv * rk;

    const long long ki = (((long long)(b * Hn + h)) * Sk + (Nq + m)) * HDim + d;
    split_write(kn, Kh, Kl, ki);
    Vb[ki] = vv;
}

__global__ void ybias_kernel(const float* __restrict__ ytw, float* __restrict__ yb)
{
    const int i = blockIdx.x * blockDim.x + threadIdx.x;
    if (i < Bsz * My) yb[i] = logf(fmaxf(ytw[i], 1e-4f));
}

// ---------------- launch ----------------
extern "C" void kernel_launch(void* const* d_in, const int* in_sizes, int n_in,
                              void* d_out, int out_size)
{
    const float* x    = (const float*)d_in[0];
    const float* y    = (const float*)d_in[1];
    const float* pos  = (const float*)d_in[2];
    const float* ytw  = (const float*)d_in[3];
    const float* Wqkv = (const float*)d_in[4];
    const float* Wkv  = (const float*)d_in[5];
    const float* qw   = (const float*)d_in[6];
    const float* kw   = (const float*)d_in[7];
    const float* Wproj= (const float*)d_in[8];
    const float* bproj= (const float*)d_in[9];
    float* out = (float*)d_out;

    float *qkv, *kvr, *Vb, *yb;
    cudaGetSymbolAddress((void**)&qkv, g_qkv);
    cudaGetSymbolAddress((void**)&kvr, g_kvr);
    cudaGetSymbolAddress((void**)&Vb,  g_Vb);
    cudaGetSymbolAddress((void**)&yb,  g_yb);

    __nv_bfloat16 *xh,*xl,*yh,*yl,*Wqh,*Wql,*Wkh,*Wkl,*Wph,*Wpl,*Obh,*Obl;
    __nv_bfloat16 *Qh,*Ql,*Kh,*Kl,*Vth,*Vtl;
    cudaGetSymbolAddress((void**)&xh, g_xh);   cudaGetSymbolAddress((void**)&xl, g_xl);
    cudaGetSymbolAddress((void**)&yh, g_yh);   cudaGetSymbolAddress((void**)&yl, g_yl);
    cudaGetSymbolAddress((void**)&Wqh, g_Wqkvh); cudaGetSymbolAddress((void**)&Wql, g_Wqkvl);
    cudaGetSymbolAddress((void**)&Wkh, g_Wkvh);  cudaGetSymbolAddress((void**)&Wkl, g_Wkvl);
    cudaGetSymbolAddress((void**)&Wph, g_Wph);   cudaGetSymbolAddress((void**)&Wpl, g_Wpl);
    cudaGetSymbolAddress((void**)&Obh, g_Obh);   cudaGetSymbolAddress((void**)&Obl, g_Obl);
    cudaGetSymbolAddress((void**)&Qh, g_Qh);     cudaGetSymbolAddress((void**)&Ql, g_Ql);
    cudaGetSymbolAddress((void**)&Kh, g_Kh);     cudaGetSymbolAddress((void**)&Kl, g_Kl);
    cudaGetSymbolAddress((void**)&Vth, g_Vth);   cudaGetSymbolAddress((void**)&Vtl, g_Vtl);

    cudaFuncSetAttribute(mma_gemm<false>, cudaFuncAttributeMaxDynamicSharedMemorySize, MM_SMEM_B);
    cudaFuncSetAttribute(mma_gemm<true>,  cudaFuncAttributeMaxDynamicSharedMemorySize, MM_SMEM_B);
    cudaFuncSetAttribute(fused_attn, cudaFuncAttributeMaxDynamicSharedMemorySize, FA_SMEM);

    // 0) split conversions
    auto cvt = [&](const float* s, __nv_bfloat16* h, __nv_bfloat16* l, long long n) {
        cvt_split<<<(int)((n / 4 + 255) / 256), 256>>>(s, h, l, n);
    };
    cvt(x, xh, xl, (long long)Bsz * Nq * Cdim);
    cvt(y, yh, yl, (long long)Bsz * My * Cdim);
    cvt_split_T<<<dim3(3 * Cdim / 32, Cdim / 32), dim3(32, 8)>>>(Wqkv, Wqh, Wql, Cdim, 3 * Cdim);
    cvt_split_T<<<dim3(2 * Cdim / 32, Cdim / 32), dim3(32, 8)>>>(Wkv,  Wkh, Wkl, Cdim, 2 * Cdim);
    cvt_split_T<<<dim3(Cdim / 32,     Cdim / 32), dim3(32, 8)>>>(Wproj, Wph, Wpl, Cdim, Cdim);

    // 1) QKV = x @ Wqkv
    mma_gemm<false><<<dim3(3 * Cdim / 128, Bsz * Nq / 128), 256, MM_SMEM_B>>>(
        xh, xl, Wqh, Wql, qkv, nullptr, Cdim, 3 * Cdim);

    // 2) KV = y @ Wkv
    mma_gemm<false><<<dim3(2 * Cdim / 128, Bsz * My / 128), 256, MM_SMEM_B>>>(
        yh, yl, Wkh, Wkl, kvr, nullptr, Cdim, 2 * Cdim);

    // 3) postprocess
    qkv_post<<<Bsz * Nq * Hn, HDim>>>(qkv, pos, qw, kw, Qh, Ql, Kh, Kl, Vb);
    kv_post<<<Bsz * My * Hn, HDim>>>(kvr, kw, Kh, Kl, Vb);
    ybias_kernel<<<(Bsz * My + 255) / 256, 256>>>(ytw, yb);
    v_transpose_split<<<dim3(Sk / 32, HDim / 32, Bsz * Hn), dim3(32, 8)>>>(Vb, Vth, Vtl);

    // 4-6) fused attention -> split-bf16 O in [b][n][h*128]
    fused_attn<<<dim3(Nq / 128, Bsz * Hn), 256, FA_SMEM>>>(
        Qh, Ql, Kh, Kl, Vth, Vtl, yb, Obh, Obl);

    // 7) out = O @ Wproj + bproj
    mma_gemm<true><<<dim3(Cdim / 128, Bsz * Nq / 128), 256, MM_SMEM_B>>>(
        Obh, Obl, Wph, Wpl, out, bproj, Cdim, Cdim);
}